// round 12
// baseline (speedup 1.0000x reference)
#include <cuda_runtime.h>
#include <math.h>
#include <stdint.h>

#define BB 8
#define NN 1024
#define CC 768
#define HH 12
#define DD 64
#define M_ROWS (BB*NN)          // 8192
#define QKV_COLS (3*CC)         // 2304
#define SCALE_Q 0.125f
#define LOG2E 1.4426950408889634f
#define LN_EPS 1e-5f

// K-contracted operands stored "k-interleaved": within each group of 8 k-values,
// order [0,4,1,5,2,6,3,7] -> mma fragment pair (k=t, k=t+4) is one LDS.64.
// V is stored TRANSPOSED [bh][d][N] with the same interleave on the token dim.

// ---------------- scratch ----------------
__device__ uint32_t g_xt[(size_t)M_ROWS * CC];        // x, tf32, k-interleaved
__device__ uint32_t g_wqkvt[(size_t)QKV_COLS * CC];   // k-interleaved
__device__ uint32_t g_wprojt[(size_t)CC * CC];        // k-interleaved
__device__ uint32_t g_q[(size_t)BB*HH*NN*DD];         // LN'd*(SCALE*LOG2E), d-interleaved
__device__ uint32_t g_k[(size_t)BB*HH*NN*DD];         // LN'd, d-interleaved
__device__ uint32_t g_v[(size_t)BB*HH*NN*DD];         // TRANSPOSED [bh][d][N], tok-interleaved
__device__ uint32_t g_y[(size_t)M_ROWS * CC];         // attn out, k-interleaved

// ---------------- helpers ----------------
__device__ __forceinline__ uint32_t f2tf(float x) {
    uint32_t u;
    asm("cvt.rna.tf32.f32 %0, %1;" : "=r"(u) : "f"(x));
    return u;
}
__device__ __forceinline__ float ex2(float x) {
    float y;
    asm("ex2.approx.f32 %0, %1;" : "=f"(y) : "f"(x));
    return y;
}
__device__ __forceinline__ void cp16(uint32_t s, const void* g) {
    asm volatile("cp.async.cg.shared.global [%0], [%1], 16;" :: "r"(s), "l"(g));
}
#define MMA_TF32(C, A0, A1, A2, A3, B0, B1)                                   \
    asm volatile(                                                             \
        "mma.sync.aligned.m16n8k8.row.col.f32.tf32.tf32.f32 "                 \
        "{%0,%1,%2,%3},{%4,%5,%6,%7},{%8,%9},{%0,%1,%2,%3};"                  \
        : "+f"(C[0]), "+f"(C[1]), "+f"(C[2]), "+f"(C[3])                      \
        : "r"(A0), "r"(A1), "r"(A2), "r"(A3), "r"(B0), "r"(B1))

// ---------------- merged fp32 -> tf32 convert + k-interleave (1 launch) ----------------
#define NX8 (M_ROWS*CC/8)
#define NW8 (QKV_COLS*CC/8)
#define NP8 (CC*CC/8)
__global__ __launch_bounds__(256) void conv_all(const float4* __restrict__ x,
                                                const float4* __restrict__ wq,
                                                const float4* __restrict__ wp,
                                                uint4* __restrict__ ox,
                                                uint4* __restrict__ owq,
                                                uint4* __restrict__ owp) {
    int i = blockIdx.x * 256 + threadIdx.x;
    const float4* in;
    uint4* out;
    int j;
    if (i < NX8) { in = x; out = ox; j = i; }
    else if (i < NX8 + NW8) { in = wq; out = owq; j = i - NX8; }
    else if (i < NX8 + NW8 + NP8) { in = wp; out = owp; j = i - NX8 - NW8; }
    else return;
    float4 a = in[2 * j];
    float4 b = in[2 * j + 1];
    out[2 * j]     = make_uint4(f2tf(a.x), f2tf(b.x), f2tf(a.y), f2tf(b.y));
    out[2 * j + 1] = make_uint4(f2tf(a.z), f2tf(b.z), f2tf(a.w), f2tf(b.w));
}

// ---------------- GEMM core (128x128 tile, GBK=16, 4-stage pipeline) ----------------
#define GBK  16
#define GSTR 24                  // stride: banks 24g+2t all-distinct per half-warp
#define STAGE_F (128*GSTR)       // 3072 u32 per stage per operand
#define NSTG 4
#define G_SMEM_U32 (NSTG*2*STAGE_F)   // 24576 u32 = 98304 B

__device__ __forceinline__ void g_load_stage(const uint32_t* __restrict__ A,
                                             const uint32_t* __restrict__ W,
                                             uint32_t sA, uint32_t sB, int st,
                                             int bm, int bn, int Kdim, int k0, int tid) {
    uint32_t dA = sA + (uint32_t)(st * 2 * STAGE_F) * 4;
    uint32_t dB = dA + (uint32_t)STAGE_F * 4;
#pragma unroll
    for (int l = 0; l < 2; l++) {
        int i = tid + l * 256;           // 0..511
        int row = i >> 2, kc = (i & 3) * 4;
        cp16(dA + (uint32_t)(row * GSTR + kc) * 4, A + (size_t)(bm + row) * Kdim + k0 + kc);
        cp16(dB + (uint32_t)(row * GSTR + kc) * 4, W + (size_t)(bn + row) * Kdim + k0 + kc);
    }
    asm volatile("cp.async.commit_group;");
}

__device__ __forceinline__ void gemm_mainloop(const uint32_t* __restrict__ A,
                                              const uint32_t* __restrict__ W,
                                              uint32_t* smem_u32,
                                              int bm, int bn, int Kdim,
                                              int tid, int wm, int wn, int g, int t,
                                              float c[4][4][4]) {
    uint32_t sA = (uint32_t)__cvta_generic_to_shared(smem_u32);
    const int KT = Kdim / GBK;           // 48
    g_load_stage(A, W, sA, sA, 0, bm, bn, Kdim, 0, tid);
    g_load_stage(A, W, sA, sA, 1, bm, bn, Kdim, GBK, tid);
    g_load_stage(A, W, sA, sA, 2, bm, bn, Kdim, 2 * GBK, tid);

    for (int kt = 0; kt < KT; kt++) {
        if (kt < KT - 2)      asm volatile("cp.async.wait_group 2;");
        else if (kt == KT - 2) asm volatile("cp.async.wait_group 1;");
        else                  asm volatile("cp.async.wait_group 0;");
        __syncthreads();
        if (kt + 3 < KT)
            g_load_stage(A, W, sA, sA, (kt + 3) & 3, bm, bn, Kdim, (kt + 3) * GBK, tid);

        const uint32_t* Ab = smem_u32 + (kt & 3) * 2 * STAGE_F;
        const uint32_t* Bb = Ab + STAGE_F;
#pragma unroll
        for (int kk = 0; kk < 2; kk++) {
            const int k8 = kk * 8;
            uint32_t af[4][4], bf[4][2];
#pragma unroll
            for (int mi = 0; mi < 4; mi++) {
                const uint32_t* p = Ab + (wm + mi * 16 + g) * GSTR + k8 + 2 * t;
                uint2 lo = *(const uint2*)p;
                uint2 hi = *(const uint2*)(p + 8 * GSTR);
                af[mi][0] = lo.x; af[mi][1] = hi.x;
                af[mi][2] = lo.y; af[mi][3] = hi.y;
            }
#pragma unroll
            for (int ni = 0; ni < 4; ni++) {
                uint2 bb = *(const uint2*)(Bb + (wn + ni * 8 + g) * GSTR + k8 + 2 * t);
                bf[ni][0] = bb.x; bf[ni][1] = bb.y;
            }
#pragma unroll
            for (int mi = 0; mi < 4; mi++)
#pragma unroll
                for (int ni = 0; ni < 4; ni++)
                    MMA_TF32(c[mi][ni], af[mi][0], af[mi][1], af[mi][2], af[mi][3],
                             bf[ni][0], bf[ni][1]);
        }
    }
}

// ---------------- proj GEMM: 128x128, fp32 output ----------------
__global__ __launch_bounds__(256, 2) void gemm_proj(const uint32_t* __restrict__ A,
                                                    const uint32_t* __restrict__ W,
                                                    float* __restrict__ Cmat,
                                                    int Mdim, int Ndim, int Kdim) {
    extern __shared__ uint32_t smu[];
    const int tid = threadIdx.x;
    const int bm = blockIdx.y * 128;
    const int bn = blockIdx.x * 128;
    const int lane = tid & 31;
    const int w = tid >> 5;
    const int wm = (w & 1) * 64;
    const int wn = (w >> 1) * 32;
    const int g = lane >> 2;
    const int t = lane & 3;

    float c[4][4][4];
#pragma unroll
    for (int mi = 0; mi < 4; mi++)
#pragma unroll
        for (int ni = 0; ni < 4; ni++)
#pragma unroll
            for (int r = 0; r < 4; r++) c[mi][ni][r] = 0.f;

    gemm_mainloop(A, W, smu, bm, bn, Kdim, tid, wm, wn, g, t, c);

#pragma unroll
    for (int mi = 0; mi < 4; mi++) {
#pragma unroll
        for (int ni = 0; ni < 4; ni++) {
            int gm = bm + wm + mi * 16 + g;
            int gn = bn + wn + ni * 8 + 2 * t;
            *(float2*)&Cmat[(size_t)gm * Ndim + gn] = make_float2(c[mi][ni][0], c[mi][ni][1]);
            *(float2*)&Cmat[(size_t)(gm + 8) * Ndim + gn] = make_float2(c[mi][ni][2], c[mi][ni][3]);
        }
    }
}

// ---------------- QKV GEMM with fused LayerNorm+split epilogue ----------------
__global__ __launch_bounds__(256, 2) void gemm_qkv_ln() {
    extern __shared__ uint32_t smu[];
    float2* psm = (float2*)(smu + G_SMEM_U32);

    const int tid = threadIdx.x;
    const int bm = blockIdx.y * 128;
    const int bn = blockIdx.x * 128;
    const int lane = tid & 31;
    const int w = tid >> 5;
    const int wm = (w & 1) * 64;
    const int wn = (w >> 1) * 32;
    const int g = lane >> 2;
    const int t = lane & 3;

    float c[4][4][4];
#pragma unroll
    for (int mi = 0; mi < 4; mi++)
#pragma unroll
        for (int ni = 0; ni < 4; ni++)
#pragma unroll
            for (int r = 0; r < 4; r++) c[mi][ni][r] = 0.f;

    gemm_mainloop(g_xt, g_wqkvt, smu, bm, bn, CC, tid, wm, wn, g, t, c);
    __syncthreads();   // all warps done with staging smem; safe to reuse

    const int s = bn / CC;
    const int colb = bn % CC;
    const int h = (colb + wn) >> 6;
    const int dbase = wn & 63;
    const int p0 = (t < 2) ? 4 * t : 4 * t - 7;

    if (s == 2) {
        // ---- V: transpose in smem, write [bh][d][N] token-interleaved ----
        uint32_t* tbuf = smu + w * 2560;    // 64 tokens x stride 40
#pragma unroll
        for (int mi = 0; mi < 4; mi++) {
#pragma unroll
            for (int r = 0; r < 2; r++) {
                int tl = mi * 16 + g + 8 * r;
#pragma unroll
                for (int ni = 0; ni < 4; ni++)
                    *(uint2*)&tbuf[tl * 40 + ni * 8 + 2 * t] =
                        make_uint2(f2tf(c[mi][ni][2 * r]), f2tf(c[mi][ni][2 * r + 1]));
            }
        }
        __syncwarp();
        int b = bm >> 10;
        int n_base = (bm & 1023) + wm;
        uint32_t* vtp = g_v + (((size_t)(b * HH + h)) * DD + dbase + lane) * NN + n_base;
#pragma unroll
        for (int p8 = 0; p8 < 8; p8++) {
            int tb = p8 * 8;
            uint4 u0, u1;
            u0.x = tbuf[(tb + 0) * 40 + lane];
            u0.y = tbuf[(tb + 4) * 40 + lane];
            u0.z = tbuf[(tb + 1) * 40 + lane];
            u0.w = tbuf[(tb + 5) * 40 + lane];
            u1.x = tbuf[(tb + 2) * 40 + lane];
            u1.y = tbuf[(tb + 6) * 40 + lane];
            u1.z = tbuf[(tb + 3) * 40 + lane];
            u1.w = tbuf[(tb + 7) * 40 + lane];
            *(uint4*)&vtp[tb] = u0;
            *(uint4*)&vtp[tb + 4] = u1;
        }
        return;
    }

    uint32_t* dst_arr = (s == 0) ? g_q : g_k;
    const int hl = wn >> 6;
    const int half = (wn >> 5) & 1;
#pragma unroll
    for (int mi = 0; mi < 4; mi++) {
#pragma unroll
        for (int r = 0; r < 2; r++) {
            float sum = 0.f, sq = 0.f;
#pragma unroll
            for (int ni = 0; ni < 4; ni++) {
                float v0 = c[mi][ni][2 * r], v1 = c[mi][ni][2 * r + 1];
                sum += v0 + v1;
                sq += v0 * v0 + v1 * v1;
            }
            sum += __shfl_xor_sync(0xffffffffu, sum, 1);
            sq  += __shfl_xor_sync(0xffffffffu, sq, 1);
            sum += __shfl_xor_sync(0xffffffffu, sum, 2);
            sq  += __shfl_xor_sync(0xffffffffu, sq, 2);
            if (t == 0) {
                int row = wm + mi * 16 + g + 8 * r;
                psm[row * 4 + hl * 2 + half] = make_float2(sum, sq);
            }
        }
    }
    __syncthreads();

    const float fscale = (s == 0) ? (SCALE_Q * LOG2E) : 1.0f;
#pragma unroll
    for (int mi = 0; mi < 4; mi++) {
#pragma unroll
        for (int r = 0; r < 2; r++) {
            int row = wm + mi * 16 + g + 8 * r;
            float2 pa = psm[row * 4 + hl * 2 + 0];
            float2 pb = psm[row * 4 + hl * 2 + 1];
            float mean = (pa.x + pb.x) * (1.f / 64.f);
            float var = (pa.y + pb.y) * (1.f / 64.f) - mean * mean;
            float sc = rsqrtf(var + LN_EPS) * fscale;
            int m = bm + row;
            int b = m >> 10, n = m & 1023;
            uint32_t* dst = dst_arr + (((size_t)(b * HH + h)) * NN + n) * DD + dbase;
#pragma unroll
            for (int ni = 0; ni < 4; ni++) {
                dst[ni * 8 + p0]     = f2tf((c[mi][ni][2 * r] - mean) * sc);
                dst[ni * 8 + p0 + 2] = f2tf((c[mi][ni][2 * r + 1] - mean) * sc);
            }
        }
    }
}

// ---------------- tensor-core flash attention (unchanged from R11) ----------
#define AST 72
#define AQ_SZ  (128*AST)
#define AKV_SZ (64*AST)
#define AK_OFF AQ_SZ
#define AV_OFF (AQ_SZ + 2*AKV_SZ)
#define A_SMEM_U32 (AQ_SZ + 4*AKV_SZ)   // 110592 B

__global__ __launch_bounds__(256, 2) void attn_mma() {
    extern __shared__ uint32_t smu[];
    uint32_t* qsu = smu;
    uint32_t* ks_ = smu + AK_OFF;
    uint32_t* vs_ = smu + AV_OFF;

    const int tid = threadIdx.x;
    const int lane = tid & 31;
    const int w = tid >> 5;
    const int g = lane >> 2;
    const int t = lane & 3;
    const int mrow = w * 16;
    const int bh = blockIdx.y;
    const int qt = blockIdx.x;
    const size_t base = (size_t)bh * NN * DD;
    const uint32_t* vtg = g_v + (size_t)bh * DD * NN;

    uint32_t sq0 = (uint32_t)__cvta_generic_to_shared(qsu);
    uint32_t sk0 = (uint32_t)__cvta_generic_to_shared(ks_);
    uint32_t sv0 = (uint32_t)__cvta_generic_to_shared(vs_);

    {
        const uint32_t* qg = g_q + base + (size_t)qt * 128 * DD;
#pragma unroll
        for (int l = 0; l < 8; l++) {
            int i = tid + l * 256;
            int row = i >> 4, c4 = (i & 15) << 2;
            cp16(sq0 + (uint32_t)(row * AST + c4) * 4, qg + row * DD + c4);
        }
        const uint32_t* kg = g_k + base;
#pragma unroll
        for (int l = 0; l < 4; l++) {
            int i = tid + l * 256;
            int row = i >> 4, c4 = (i & 15) << 2;
            cp16(sk0 + (uint32_t)(row * AST + c4) * 4, kg + row * DD + c4);
            cp16(sv0 + (uint32_t)(row * AST + c4) * 4, vtg + (size_t)row * NN + c4);
        }
        asm volatile("cp.async.commit_group;");
    }

    float l0p = 0.f, l1p = 0.f;
    float o[8][4];
#pragma unroll
    for (int ni = 0; ni < 8; ni++)
#pragma unroll
        for (int r = 0; r < 4; r++) o[ni][r] = 0.f;

    const int r0 = mrow + g, r1 = mrow + g + 8;
    const int srcA = (lane & ~3) | (t >> 1);

    for (int tkv = 0; tkv < 16; tkv++) {
        asm volatile("cp.async.wait_group 0;");
        __syncthreads();

        if (tkv + 1 < 16) {
            int st = (tkv + 1) & 1;
            const uint32_t* kg = g_k + base + (size_t)(tkv + 1) * 64 * DD;
            const uint32_t* vg = vtg + (tkv + 1) * 64;
            uint32_t dk = sk0 + (uint32_t)(st * AKV_SZ) * 4;
            uint32_t dv = sv0 + (uint32_t)(st * AKV_SZ) * 4;
#pragma unroll
            for (int l = 0; l < 4; l++) {
                int i = tid + l * 256;
                int row = i >> 4, c4 = (i & 15) << 2;
                cp16(dk + (uint32_t)(row * AST + c4) * 4, kg + row * DD + c4);
                cp16(dv + (uint32_t)(row * AST + c4) * 4, vg + (size_t)row * NN + c4);
            }
            asm volatile("cp.async.commit_group;");
        }

        const uint32_t* K = ks_ + (tkv & 1) * AKV_SZ;
        const uint32_t* V = vs_ + (tkv & 1) * AKV_SZ;

        float s[8][4];
#pragma unroll
        for (int ni = 0; ni < 8; ni++)
#pragma unroll
            for (int r = 0; r < 4; r++) s[ni][r] = 0.f;

#pragma unroll
        for (int kk = 0; kk < 8; kk++) {
            const int k8 = kk * 8;
            uint2 qa = *(const uint2*)&qsu[r0 * AST + k8 + 2 * t];
            uint2 qb = *(const uint2*)&qsu[r1 * AST + k8 + 2 * t];
#pragma unroll
            for (int ni = 0; ni < 8; ni++) {
                uint2 kb = *(const uint2*)&K[(ni * 8 + g) * AST + k8 + 2 * t];
                MMA_TF32(s[ni], qa.x, qb.x, qa.y, qb.y, kb.x, kb.y);
            }
        }

#pragma unroll
        for (int kk = 0; kk < 8; kk++) {
            const int k8 = kk * 8;
            float p0 = ex2(s[kk][0]);
            float p1 = ex2(s[kk][1]);
            float p2 = ex2(s[kk][2]);
            float p3 = ex2(s[kk][3]);
            l0p += p0 + p1;
            l1p += p2 + p3;
            uint32_t pu0 = f2tf(p0), pu1 = f2tf(p1), pu2 = f2tf(p2), pu3 = f2tf(p3);

            uint32_t e00 = __shfl_sync(0xffffffffu, pu0, srcA);
            uint32_t e01 = __shfl_sync(0xffffffffu, pu1, srcA);
            uint32_t e10 = __shfl_sync(0xffffffffu, pu0, srcA + 2);
            uint32_t e11 = __shfl_sync(0xffffffffu, pu1, srcA + 2);
            uint32_t f00 = __shfl_sync(0xffffffffu, pu2, srcA);
            uint32_t f01 = __shfl_sync(0xffffffffu, pu3, srcA);
            uint32_t f10 = __shfl_sync(0xffffffffu, pu2, srcA + 2);
            uint32_t f11 = __shfl_sync(0xffffffffu, pu3, srcA + 2);
            uint32_t a0 = (t & 1) ? e01 : e00;
            uint32_t a2 = (t & 1) ? e11 : e10;
            uint32_t a1 = (t & 1) ? f01 : f00;
            uint32_t a3 = (t & 1) ? f11 : f10;
#pragma unroll
            for (int ni = 0; ni < 8; ni++) {
                uint2 vb = *(const uint2*)&V[(ni * 8 + g) * AST + k8 + 2 * t];
                MMA_TF32(o[ni], a0, a1, a2, a3, vb.x, vb.y);
            }
        }
    }

    float l0 = l0p, l1 = l1p;
    l0 += __shfl_xor_sync(0xffffffffu, l0, 1);
    l0 += __shfl_xor_sync(0xffffffffu, l0, 2);
    l1 += __shfl_xor_sync(0xffffffffu, l1, 1);
    l1 += __shfl_xor_sync(0xffffffffu, l1, 2);

    int b = bh / HH, h = bh % HH;
    float inv0 = 1.f / l0, inv1 = 1.f / l1;
    int n0 = qt * 128 + r0, n1 = qt * 128 + r1;
    uint32_t* y0 = g_y + ((size_t)(b * NN + n0)) * CC + h * DD;
    uint32_t* y1 = g_y + ((size_t)(b * NN + n1)) * CC + h * DD;
    const int p0i = (t < 2) ? 4 * t : 4 * t - 7;
#pragma unroll
    for (int ni = 0; ni < 8; ni++) {
        y0[ni * 8 + p0i]     = f2tf(o[ni][0] * inv0);
        y0[ni * 8 + p0i + 2] = f2tf(o[ni][1] * inv0);
        y1[ni * 8 + p0i]     = f2tf(o[ni][2] * inv1);
        y1[ni * 8 + p0i + 2] = f2tf(o[ni][3] * inv1);
    }
}

// ---------------- launch ----------------
extern "C" void kernel_launch(void* const* d_in, const int* in_sizes, int n_in,
                              void* d_out, int out_size) {
    const float* x     = (const float*)d_in[0];
    const float* wqkv  = (const float*)d_in[1];
    const float* wproj = (const float*)d_in[2];
    float* out = (float*)d_out;

    void *p_xt, *p_wqkvt, *p_wprojt, *p_y;
    cudaGetSymbolAddress(&p_xt, g_xt);
    cudaGetSymbolAddress(&p_wqkvt, g_wqkvt);
    cudaGetSymbolAddress(&p_wprojt, g_wprojt);
    cudaGetSymbolAddress(&p_y, g_y);

    const int gemm_smem = G_SMEM_U32 * (int)sizeof(uint32_t);          // 98304
    const int qkv_smem  = gemm_smem + 128 * 4 * (int)sizeof(float2);   // +4096
    const int attn_smem = A_SMEM_U32 * (int)sizeof(uint32_t);          // 110592
    cudaFuncSetAttribute(gemm_proj, cudaFuncAttributeMaxDynamicSharedMemorySize, gemm_smem);
    cudaFuncSetAttribute(gemm_qkv_ln, cudaFuncAttributeMaxDynamicSharedMemorySize, qkv_smem);
    cudaFuncSetAttribute(attn_mma, cudaFuncAttributeMaxDynamicSharedMemorySize, attn_smem);

    // 0) convert all inputs to tf32 (k-interleaved) in ONE launch
    {
        int total = NX8 + NW8 + NP8;
        conv_all<<<(total + 255) / 256, 256>>>((const float4*)x, (const float4*)wqkv,
                                               (const float4*)wproj,
                                               (uint4*)p_xt, (uint4*)p_wqkvt, (uint4*)p_wprojt);
    }
    // 1) QKV GEMM + fused LN/split (+ V transpose)
    {
        dim3 grid(QKV_COLS / 128, M_ROWS / 128);   // (18, 64)
        gemm_qkv_ln<<<grid, 256, qkv_smem>>>();
    }
    // 2) Attention
    {
        dim3 grid(NN / 128, BB * HH);              // (8, 96)
        attn_mma<<<grid, 256, attn_smem>>>();
    }
    // 3) Output projection
    {
        dim3 grid(CC / 128, M_ROWS / 128);         // (6, 64)
        gemm_proj<<<grid, 256, gemm_smem>>>((const uint32_t*)p_y, (const uint32_t*)p_wprojt,
                                            out, M_ROWS, CC, CC);
    }
}

// round 13
// speedup vs baseline: 1.0887x; 1.0887x over previous
#include <cuda_runtime.h>
#include <math.h>
#include <stdint.h>

#define BB 8
#define NN 1024
#define CC 768
#define HH 12
#define DD 64
#define M_ROWS (BB*NN)          // 8192
#define QKV_COLS (3*CC)         // 2304
#define SCALE_Q 0.125f
#define LOG2E 1.4426950408889634f
#define LN_EPS 1e-5f

// Layout invariants:
//  - K-contracted operands "k-interleaved": within each 8-group, order
//    [0,4,1,5,2,6,3,7] -> mma frag pair (k=t,k=t+4) is one LDS.64.
//  - V TRANSPOSED [bh][d][N], token dim interleaved the same way.
//  - K rows TOKEN-PERMUTED within 8-groups (token T at row T<4?2T:2T-7) so the
//    QK C-fragment is directly the PV A-fragment (no shuffles).

// ---------------- scratch ----------------
__device__ uint32_t g_xt[(size_t)M_ROWS * CC];        // x, tf32, k-interleaved
__device__ uint32_t g_wqkvt[(size_t)QKV_COLS * CC];   // k-interleaved
__device__ uint32_t g_wprojt[(size_t)CC * CC];        // k-interleaved
__device__ uint32_t g_q[(size_t)BB*HH*NN*DD];         // LN'd*(SCALE*LOG2E), d-interleaved
__device__ uint32_t g_k[(size_t)BB*HH*NN*DD];         // LN'd, d-interleaved, row-permuted
__device__ uint32_t g_v[(size_t)BB*HH*NN*DD];         // TRANSPOSED [bh][d][N], tok-interleaved
__device__ uint32_t g_y[(size_t)M_ROWS * CC];         // attn out, k-interleaved

// ---------------- helpers ----------------
__device__ __forceinline__ uint32_t f2tf(float x) {
    uint32_t u;
    asm("cvt.rna.tf32.f32 %0, %1;" : "=r"(u) : "f"(x));
    return u;
}
__device__ __forceinline__ float ex2(float x) {
    float y;
    asm("ex2.approx.f32 %0, %1;" : "=f"(y) : "f"(x));
    return y;
}
__device__ __forceinline__ void cp16(uint32_t s, const void* g) {
    asm volatile("cp.async.cg.shared.global [%0], [%1], 16;" :: "r"(s), "l"(g));
}
#define MMA_TF32(C, A0, A1, A2, A3, B0, B1)                                   \
    asm volatile(                                                             \
        "mma.sync.aligned.m16n8k8.row.col.f32.tf32.tf32.f32 "                 \
        "{%0,%1,%2,%3},{%4,%5,%6,%7},{%8,%9},{%0,%1,%2,%3};"                  \
        : "+f"(C[0]), "+f"(C[1]), "+f"(C[2]), "+f"(C[3])                      \
        : "r"(A0), "r"(A1), "r"(A2), "r"(A3), "r"(B0), "r"(B1))

// ---------------- merged fp32 -> tf32 convert + k-interleave (1 launch) ----------------
#define NX8 (M_ROWS*CC/8)
#define NW8 (QKV_COLS*CC/8)
#define NP8 (CC*CC/8)
__global__ __launch_bounds__(256) void conv_all(const float4* __restrict__ x,
                                                const float4* __restrict__ wq,
                                                const float4* __restrict__ wp,
                                                uint4* __restrict__ ox,
                                                uint4* __restrict__ owq,
                                                uint4* __restrict__ owp) {
    int i = blockIdx.x * 256 + threadIdx.x;
    const float4* in;
    uint4* out;
    int j;
    if (i < NX8) { in = x; out = ox; j = i; }
    else if (i < NX8 + NW8) { in = wq; out = owq; j = i - NX8; }
    else if (i < NX8 + NW8 + NP8) { in = wp; out = owp; j = i - NX8 - NW8; }
    else return;
    float4 a = in[2 * j];
    float4 b = in[2 * j + 1];
    out[2 * j]     = make_uint4(f2tf(a.x), f2tf(b.x), f2tf(a.y), f2tf(b.y));
    out[2 * j + 1] = make_uint4(f2tf(a.z), f2tf(b.z), f2tf(a.w), f2tf(b.w));
}

// ---------------- GEMM core (R11: 128x128, GBK=32, 2-stage, occ 2) ----------------
#define GBK  32
#define GSTR 40
#define TILE_F (128*GSTR)       // 5120 u32 per stage per operand

__device__ __forceinline__ void gemm_mainloop(const uint32_t* __restrict__ A,
                                              const uint32_t* __restrict__ W,
                                              uint32_t* As, uint32_t* Bs,
                                              int bm, int bn, int Kdim,
                                              int tid, int wm, int wn, int g, int t,
                                              float c[4][4][4]) {
    uint32_t sA0 = (uint32_t)__cvta_generic_to_shared(As);
    uint32_t sB0 = (uint32_t)__cvta_generic_to_shared(Bs);
    const int KT = Kdim / GBK;
    {
#pragma unroll
        for (int l = 0; l < 4; l++) {
            int i = tid + l * 256;
            int m = i >> 3, kc = (i & 7) * 4;
            cp16(sA0 + (uint32_t)(m * GSTR + kc) * 4, A + (size_t)(bm + m) * Kdim + kc);
            cp16(sB0 + (uint32_t)(m * GSTR + kc) * 4, W + (size_t)(bn + m) * Kdim + kc);
        }
        asm volatile("cp.async.commit_group;");
    }
    for (int kt = 0; kt < KT; kt++) {
        int buf = kt & 1;
        asm volatile("cp.async.wait_group 0;");
        __syncthreads();
        if (kt + 1 < KT) {
            int k0 = (kt + 1) * GBK;
            uint32_t dA = sA0 + (uint32_t)((buf ^ 1) * TILE_F) * 4;
            uint32_t dB = sB0 + (uint32_t)((buf ^ 1) * TILE_F) * 4;
#pragma unroll
            for (int l = 0; l < 4; l++) {
                int i = tid + l * 256;
                int m = i >> 3, kc = (i & 7) * 4;
                cp16(dA + (uint32_t)(m * GSTR + kc) * 4, A + (size_t)(bm + m) * Kdim + k0 + kc);
                cp16(dB + (uint32_t)(m * GSTR + kc) * 4, W + (size_t)(bn + m) * Kdim + k0 + kc);
            }
            asm volatile("cp.async.commit_group;");
        }

        const uint32_t* Ab = As + buf * TILE_F;
        const uint32_t* Bb = Bs + buf * TILE_F;
#pragma unroll
        for (int kk = 0; kk < 4; kk++) {
            const int k8 = kk * 8;
            uint32_t af[4][4], bf[4][2];
#pragma unroll
            for (int mi = 0; mi < 4; mi++) {
                const uint32_t* p = Ab + (wm + mi * 16 + g) * GSTR + k8 + 2 * t;
                uint2 lo = *(const uint2*)p;
                uint2 hi = *(const uint2*)(p + 8 * GSTR);
                af[mi][0] = lo.x; af[mi][1] = hi.x;
                af[mi][2] = lo.y; af[mi][3] = hi.y;
            }
#pragma unroll
            for (int ni = 0; ni < 4; ni++) {
                uint2 bb = *(const uint2*)(Bb + (wn + ni * 8 + g) * GSTR + k8 + 2 * t);
                bf[ni][0] = bb.x; bf[ni][1] = bb.y;
            }
#pragma unroll
            for (int mi = 0; mi < 4; mi++)
#pragma unroll
                for (int ni = 0; ni < 4; ni++)
                    MMA_TF32(c[mi][ni], af[mi][0], af[mi][1], af[mi][2], af[mi][3],
                             bf[ni][0], bf[ni][1]);
        }
    }
}

// ---------------- proj GEMM: 128x128, fp32 output ----------------
__global__ __launch_bounds__(256, 2) void gemm_proj(const uint32_t* __restrict__ A,
                                                    const uint32_t* __restrict__ W,
                                                    float* __restrict__ Cmat,
                                                    int Mdim, int Ndim, int Kdim) {
    extern __shared__ uint32_t smu[];
    uint32_t* As = smu;
    uint32_t* Bs = smu + 2 * TILE_F;
    const int tid = threadIdx.x;
    const int bm = blockIdx.y * 128;
    const int bn = blockIdx.x * 128;
    const int lane = tid & 31;
    const int w = tid >> 5;
    const int wm = (w & 1) * 64;
    const int wn = (w >> 1) * 32;
    const int g = lane >> 2;
    const int t = lane & 3;

    float c[4][4][4];
#pragma unroll
    for (int mi = 0; mi < 4; mi++)
#pragma unroll
        for (int ni = 0; ni < 4; ni++)
#pragma unroll
            for (int r = 0; r < 4; r++) c[mi][ni][r] = 0.f;

    gemm_mainloop(A, W, As, Bs, bm, bn, Kdim, tid, wm, wn, g, t, c);

#pragma unroll
    for (int mi = 0; mi < 4; mi++) {
#pragma unroll
        for (int ni = 0; ni < 4; ni++) {
            int gm = bm + wm + mi * 16 + g;
            int gn = bn + wn + ni * 8 + 2 * t;
            *(float2*)&Cmat[(size_t)gm * Ndim + gn] = make_float2(c[mi][ni][0], c[mi][ni][1]);
            *(float2*)&Cmat[(size_t)(gm + 8) * Ndim + gn] = make_float2(c[mi][ni][2], c[mi][ni][3]);
        }
    }
}

// ---------------- QKV GEMM with fused LayerNorm+split epilogue ----------------
// q: LN, d-interleaved.  k: LN, d-interleaved + TOKEN ROW PERMUTATION within 8-groups
// (token g -> row g<4 ? 2g : 2g-7), so attn's QK C-frag is directly the PV A-frag.
// v: transposed [bh][d][N], token-interleaved.
__global__ __launch_bounds__(256, 2) void gemm_qkv_ln() {
    extern __shared__ uint32_t smu[];
    uint32_t* As = smu;
    uint32_t* Bs = smu + 2 * TILE_F;
    float2* psm = (float2*)(smu + 4 * TILE_F);

    const int tid = threadIdx.x;
    const int bm = blockIdx.y * 128;
    const int bn = blockIdx.x * 128;
    const int lane = tid & 31;
    const int w = tid >> 5;
    const int wm = (w & 1) * 64;
    const int wn = (w >> 1) * 32;
    const int g = lane >> 2;
    const int t = lane & 3;

    float c[4][4][4];
#pragma unroll
    for (int mi = 0; mi < 4; mi++)
#pragma unroll
        for (int ni = 0; ni < 4; ni++)
#pragma unroll
            for (int r = 0; r < 4; r++) c[mi][ni][r] = 0.f;

    gemm_mainloop(g_xt, g_wqkvt, As, Bs, bm, bn, CC, tid, wm, wn, g, t, c);
    __syncthreads();   // all warps done with As/Bs; safe to reuse smem

    const int s = bn / CC;
    const int colb = bn % CC;
    const int h = (colb + wn) >> 6;
    const int dbase = wn & 63;
    const int p0 = (t < 2) ? 4 * t : 4 * t - 7;

    if (s == 2) {
        // ---- V: transpose in smem, write [bh][d][N] token-interleaved ----
        uint32_t* tbuf = smu + w * 2560;    // 64 tokens x stride 40
#pragma unroll
        for (int mi = 0; mi < 4; mi++) {
#pragma unroll
            for (int r = 0; r < 2; r++) {
                int tl = mi * 16 + g + 8 * r;
#pragma unroll
                for (int ni = 0; ni < 4; ni++)
                    *(uint2*)&tbuf[tl * 40 + ni * 8 + 2 * t] =
                        make_uint2(f2tf(c[mi][ni][2 * r]), f2tf(c[mi][ni][2 * r + 1]));
            }
        }
        __syncwarp();
        int b = bm >> 10;
        int n_base = (bm & 1023) + wm;
        uint32_t* vtp = g_v + (((size_t)(b * HH + h)) * DD + dbase + lane) * NN + n_base;
#pragma unroll
        for (int p8 = 0; p8 < 8; p8++) {
            int tb = p8 * 8;
            uint4 u0, u1;
            u0.x = tbuf[(tb + 0) * 40 + lane];
            u0.y = tbuf[(tb + 4) * 40 + lane];
            u0.z = tbuf[(tb + 1) * 40 + lane];
            u0.w = tbuf[(tb + 5) * 40 + lane];
            u1.x = tbuf[(tb + 2) * 40 + lane];
            u1.y = tbuf[(tb + 6) * 40 + lane];
            u1.z = tbuf[(tb + 3) * 40 + lane];
            u1.w = tbuf[(tb + 7) * 40 + lane];
            *(uint4*)&vtp[tb] = u0;
            *(uint4*)&vtp[tb + 4] = u1;
        }
        return;
    }

    uint32_t* dst_arr = (s == 0) ? g_q : g_k;
    // K token row permutation: token (n&7)==g goes to row perm(g)=g<4?2g:2g-7
    const int krow = (g < 4) ? 2 * g : 2 * g - 7;
    const int hl = wn >> 6;
    const int half = (wn >> 5) & 1;
#pragma unroll
    for (int mi = 0; mi < 4; mi++) {
#pragma unroll
        for (int r = 0; r < 2; r++) {
            float sum = 0.f, sq = 0.f;
#pragma unroll
            for (int ni = 0; ni < 4; ni++) {
                float v0 = c[mi][ni][2 * r], v1 = c[mi][ni][2 * r + 1];
                sum += v0 + v1;
                sq += v0 * v0 + v1 * v1;
            }
            sum += __shfl_xor_sync(0xffffffffu, sum, 1);
            sq  += __shfl_xor_sync(0xffffffffu, sq, 1);
            sum += __shfl_xor_sync(0xffffffffu, sum, 2);
            sq  += __shfl_xor_sync(0xffffffffu, sq, 2);
            if (t == 0) {
                int row = wm + mi * 16 + g + 8 * r;
                psm[row * 4 + hl * 2 + half] = make_float2(sum, sq);
            }
        }
    }
    __syncthreads();

    const float fscale = (s == 0) ? (SCALE_Q * LOG2E) : 1.0f;
#pragma unroll
    for (int mi = 0; mi < 4; mi++) {
#pragma unroll
        for (int r = 0; r < 2; r++) {
            int row = wm + mi * 16 + g + 8 * r;
            float2 pa = psm[row * 4 + hl * 2 + 0];
            float2 pb = psm[row * 4 + hl * 2 + 1];
            float mean = (pa.x + pb.x) * (1.f / 64.f);
            float var = (pa.y + pb.y) * (1.f / 64.f) - mean * mean;
            float sc = rsqrtf(var + LN_EPS) * fscale;
            int m = bm + row;
            int b = m >> 10, n = m & 1023;
            int nd = (s == 1) ? ((n & ~7) | krow) : n;     // K: permuted row
            uint32_t* dst = dst_arr + (((size_t)(b * HH + h)) * NN + nd) * DD + dbase;
#pragma unroll
            for (int ni = 0; ni < 4; ni++) {
                dst[ni * 8 + p0]     = f2tf((c[mi][ni][2 * r] - mean) * sc);
                dst[ni * 8 + p0 + 2] = f2tf((c[mi][ni][2 * r + 1] - mean) * sc);
            }
        }
    }
}

// ---------------- tensor-core flash attention (shuffle-free PV) ----------
#define AST 72
#define AQ_SZ  (128*AST)
#define AKV_SZ (64*AST)
#define AK_OFF AQ_SZ
#define AV_OFF (AQ_SZ + 2*AKV_SZ)
#define A_SMEM_U32 (AQ_SZ + 4*AKV_SZ)   // 110592 B

__global__ __launch_bounds__(256, 2) void attn_mma() {
    extern __shared__ uint32_t smu[];
    uint32_t* qsu = smu;
    uint32_t* ks_ = smu + AK_OFF;
    uint32_t* vs_ = smu + AV_OFF;

    const int tid = threadIdx.x;
    const int lane = tid & 31;
    const int w = tid >> 5;
    const int g = lane >> 2;
    const int t = lane & 3;
    const int mrow = w * 16;
    const int bh = blockIdx.y;
    const int qt = blockIdx.x;
    const size_t base = (size_t)bh * NN * DD;
    const uint32_t* vtg = g_v + (size_t)bh * DD * NN;

    uint32_t sq0 = (uint32_t)__cvta_generic_to_shared(qsu);
    uint32_t sk0 = (uint32_t)__cvta_generic_to_shared(ks_);
    uint32_t sv0 = (uint32_t)__cvta_generic_to_shared(vs_);

    {
        const uint32_t* qg = g_q + base + (size_t)qt * 128 * DD;
#pragma unroll
        for (int l = 0; l < 8; l++) {
            int i = tid + l * 256;
            int row = i >> 4, c4 = (i & 15) << 2;
            cp16(sq0 + (uint32_t)(row * AST + c4) * 4, qg + row * DD + c4);
        }
        const uint32_t* kg = g_k + base;
#pragma unroll
        for (int l = 0; l < 4; l++) {
            int i = tid + l * 256;
            int row = i >> 4, c4 = (i & 15) << 2;
            cp16(sk0 + (uint32_t)(row * AST + c4) * 4, kg + row * DD + c4);
            cp16(sv0 + (uint32_t)(row * AST + c4) * 4, vtg + (size_t)row * NN + c4);
        }
        asm volatile("cp.async.commit_group;");
    }

    float l0p = 0.f, l1p = 0.f;
    float o[8][4];
#pragma unroll
    for (int ni = 0; ni < 8; ni++)
#pragma unroll
        for (int r = 0; r < 4; r++) o[ni][r] = 0.f;

    const int r0 = mrow + g, r1 = mrow + g + 8;

    for (int tkv = 0; tkv < 16; tkv++) {
        asm volatile("cp.async.wait_group 0;");
        __syncthreads();

        if (tkv + 1 < 16) {
            int st = (tkv + 1) & 1;
            const uint32_t* kg = g_k + base + (size_t)(tkv + 1) * 64 * DD;
            const uint32_t* vg = vtg + (tkv + 1) * 64;
            uint32_t dk = sk0 + (uint32_t)(st * AKV_SZ) * 4;
            uint32_t dv = sv0 + (uint32_t)(st * AKV_SZ) * 4;
#pragma unroll
            for (int l = 0; l < 4; l++) {
                int i = tid + l * 256;
                int row = i >> 4, c4 = (i & 15) << 2;
                cp16(dk + (uint32_t)(row * AST + c4) * 4, kg + row * DD + c4);
                cp16(dv + (uint32_t)(row * AST + c4) * 4, vg + (size_t)row * NN + c4);
            }
            asm volatile("cp.async.commit_group;");
        }

        const uint32_t* K = ks_ + (tkv & 1) * AKV_SZ;
        const uint32_t* V = vs_ + (tkv & 1) * AKV_SZ;

        // ---- S = Q @ K^T (K rows are token-permuted) ----
        float s[8][4];
#pragma unroll
        for (int ni = 0; ni < 8; ni++)
#pragma unroll
            for (int r = 0; r < 4; r++) s[ni][r] = 0.f;

#pragma unroll
        for (int kk = 0; kk < 8; kk++) {
            const int k8 = kk * 8;
            uint2 qa = *(const uint2*)&qsu[r0 * AST + k8 + 2 * t];
            uint2 qb = *(const uint2*)&qsu[r1 * AST + k8 + 2 * t];
#pragma unroll
            for (int ni = 0; ni < 8; ni++) {
                uint2 kb = *(const uint2*)&K[(ni * 8 + g) * AST + k8 + 2 * t];
                MMA_TF32(s[ni], qa.x, qb.x, qa.y, qb.y, kb.x, kb.y);
            }
        }

        // ---- P = exp2(S), used DIRECTLY as PV A-frags (no shuffles) ----
#pragma unroll
        for (int kk = 0; kk < 8; kk++) {
            const int k8 = kk * 8;
            float p0 = ex2(s[kk][0]);
            float p1 = ex2(s[kk][1]);
            float p2 = ex2(s[kk][2]);
            float p3 = ex2(s[kk][3]);
            l0p += p0 + p1;
            l1p += p2 + p3;
            uint32_t a0 = f2tf(p0);    // P[r0][slot t]
            uint32_t a1 = f2tf(p2);    // P[r1][slot t]
            uint32_t a2 = f2tf(p1);    // P[r0][slot t+4]
            uint32_t a3 = f2tf(p3);    // P[r1][slot t+4]
#pragma unroll
            for (int ni = 0; ni < 8; ni++) {
                uint2 vb = *(const uint2*)&V[(ni * 8 + g) * AST + k8 + 2 * t];
                MMA_TF32(o[ni], a0, a1, a2, a3, vb.x, vb.y);
            }
        }
    }

    float l0 = l0p, l1 = l1p;
    l0 += __shfl_xor_sync(0xffffffffu, l0, 1);
    l0 += __shfl_xor_sync(0xffffffffu, l0, 2);
    l1 += __shfl_xor_sync(0xffffffffu, l1, 1);
    l1 += __shfl_xor_sync(0xffffffffu, l1, 2);

    int b = bh / HH, h = bh % HH;
    float inv0 = 1.f / l0, inv1 = 1.f / l1;
    int n0 = qt * 128 + r0, n1 = qt * 128 + r1;
    uint32_t* y0 = g_y + ((size_t)(b * NN + n0)) * CC + h * DD;
    uint32_t* y1 = g_y + ((size_t)(b * NN + n1)) * CC + h * DD;
    const int p0i = (t < 2) ? 4 * t : 4 * t - 7;
#pragma unroll
    for (int ni = 0; ni < 8; ni++) {
        y0[ni * 8 + p0i]     = f2tf(o[ni][0] * inv0);
        y0[ni * 8 + p0i + 2] = f2tf(o[ni][1] * inv0);
        y1[ni * 8 + p0i]     = f2tf(o[ni][2] * inv1);
        y1[ni * 8 + p0i + 2] = f2tf(o[ni][3] * inv1);
    }
}

// ---------------- launch ----------------
extern "C" void kernel_launch(void* const* d_in, const int* in_sizes, int n_in,
                              void* d_out, int out_size) {
    const float* x     = (const float*)d_in[0];
    const float* wqkv  = (const float*)d_in[1];
    const float* wproj = (const float*)d_in[2];
    float* out = (float*)d_out;

    void *p_xt, *p_wqkvt, *p_wprojt, *p_y;
    cudaGetSymbolAddress(&p_xt, g_xt);
    cudaGetSymbolAddress(&p_wqkvt, g_wqkvt);
    cudaGetSymbolAddress(&p_wprojt, g_wprojt);
    cudaGetSymbolAddress(&p_y, g_y);

    const int gemm_smem = 4 * TILE_F * (int)sizeof(uint32_t);          // 81920
    const int qkv_smem  = gemm_smem + 128 * 4 * (int)sizeof(float2);   // +4096
    const int attn_smem = A_SMEM_U32 * (int)sizeof(uint32_t);          // 110592
    cudaFuncSetAttribute(gemm_proj, cudaFuncAttributeMaxDynamicSharedMemorySize, gemm_smem);
    cudaFuncSetAttribute(gemm_qkv_ln, cudaFuncAttributeMaxDynamicSharedMemorySize, qkv_smem);
    cudaFuncSetAttribute(attn_mma, cudaFuncAttributeMaxDynamicSharedMemorySize, attn_smem);

    // 0) convert all inputs to tf32 (k-interleaved) in ONE launch
    {
        int total = NX8 + NW8 + NP8;
        conv_all<<<(total + 255) / 256, 256>>>((const float4*)x, (const float4*)wqkv,
                                               (const float4*)wproj,
                                               (uint4*)p_xt, (uint4*)p_wqkvt, (uint4*)p_wprojt);
    }
    // 1) QKV GEMM + fused LN/split (+ V transpose, K row-perm)
    {
        dim3 grid(QKV_COLS / 128, M_ROWS / 128);   // (18, 64)
        gemm_qkv_ln<<<grid, 256, qkv_smem>>>();
    }
    // 2) Attention
    {
        dim3 grid(NN / 128, BB * HH);              // (8, 96)
        attn_mma<<<grid, 256, attn_smem>>>();
    }
    // 3) Output projection
    {
        dim3 grid(CC / 128, M_ROWS / 128);         // (6, 64)
        gemm_proj<<<grid, 256, gemm_smem>>>((const uint32_t*)p_y, (const uint32_t*)p_wprojt,
                                            out, M_ROWS, CC, CC);
    }
}